// round 3
// baseline (speedup 1.0000x reference)
#include <cuda_runtime.h>

#define F_IN  14
#define HEADS 8
#define DIM   8
#define F1    64          // HEADS*DIM
#define NEG   0.2f
#define MAXN  100000
#define MAXE  1600000

// ------------------------- scratch (device globals; no allocs) -------------
__device__ float g_h1  [MAXN * F1];     // layer1 linear output [N,64]
__device__ float g_out1[MAXN * F1];     // layer1 aggregated (then ELU'd) [N,64]
__device__ float g_as1 [MAXN * HEADS];
__device__ float g_ad1 [MAXN * HEADS];
__device__ float g_m1  [MAXN * HEADS];
__device__ float g_s1  [MAXN * HEADS];
__device__ float g_h2  [MAXN * DIM];    // layer2 linear output [N,8]
__device__ float g_as2 [MAXN];
__device__ float g_ad2 [MAXN];
__device__ float g_m2  [MAXN];
__device__ float g_s2  [MAXN];
__device__ int   g_src [MAXE];
__device__ int   g_dst [MAXE];
__device__ int   g_is64;

// ------------------------- helpers ----------------------------------------
__device__ __forceinline__ float lrelu(float x) { return x > 0.f ? x : NEG * x; }

// float atomic max via int-max / uint-min idiom (no NaNs in this workload)
__device__ __forceinline__ void atomicMaxF(float* a, float v) {
    if (v >= 0.f) atomicMax((int*)a, __float_as_int(v));
    else          atomicMin((unsigned int*)a, __float_as_uint(v));
}

// vectorized global reduction (sm_90+): 4 floats per RED op
__device__ __forceinline__ void redAdd4(float* a, float x, float y, float z, float w) {
    asm volatile("red.global.add.v4.f32 [%0], {%1,%2,%3,%4};"
                 :: "l"(a), "f"(x), "f"(y), "f"(z), "f"(w) : "memory");
}

// ------------------------- edge dtype detect + convert ---------------------
__global__ void k_detect(const unsigned long long* p) {
    if (threadIdx.x == 0) {
        int is64 = 1;
        for (int i = 0; i < 64; i++)
            if (p[i] >> 32) { is64 = 0; break; }
        g_is64 = is64;
    }
}

__global__ void k_convert(const void* ei, int e) {
    int i = blockIdx.x * blockDim.x + threadIdx.x;
    if (i >= e) return;
    if (g_is64) {
        const long long* p = (const long long*)ei;
        g_src[i] = (int)p[i];
        g_dst[i] = (int)p[e + i];
    } else {
        const int* p = (const int*)ei;
        g_src[i] = p[i];
        g_dst[i] = p[e + i];
    }
}

// ------------------------- layer 1 ----------------------------------------
// h1 = x @ W1   (thread per (node, outcol))
__global__ void k_gemm1(const float* __restrict__ x, const float* __restrict__ W1, int n) {
    __shared__ float sW[F_IN * F1];
    for (int i = threadIdx.x; i < F_IN * F1; i += blockDim.x) sW[i] = W1[i];
    __syncthreads();
    int i = blockIdx.x * blockDim.x + threadIdx.x;
    if (i >= n * F1) return;
    int node = i >> 6, c = i & 63;
    const float* xr = x + node * F_IN;
    float acc = 0.f;
#pragma unroll
    for (int k = 0; k < F_IN; k++) acc += xr[k] * sW[k * F1 + c];
    g_h1[i] = acc;
}

// per (node, head): attention logit halves + self-loop max init
__global__ void k_alpha1(const float* __restrict__ asrc, const float* __restrict__ adst, int n) {
    __shared__ float sS[64], sD[64];
    if (threadIdx.x < 64) { sS[threadIdx.x] = asrc[threadIdx.x]; sD[threadIdx.x] = adst[threadIdx.x]; }
    __syncthreads();
    int i = blockIdx.x * blockDim.x + threadIdx.x;
    if (i >= n * HEADS) return;
    int h = i & 7;
    float4 v0 = *(const float4*)(g_h1 + i * 8);
    float4 v1 = *(const float4*)(g_h1 + i * 8 + 4);
    const float* S = sS + h * 8;
    const float* D = sD + h * 8;
    float as = v0.x*S[0] + v0.y*S[1] + v0.z*S[2] + v0.w*S[3]
             + v1.x*S[4] + v1.y*S[5] + v1.z*S[6] + v1.w*S[7];
    float ad = v0.x*D[0] + v0.y*D[1] + v0.z*D[2] + v0.w*D[3]
             + v1.x*D[4] + v1.y*D[5] + v1.z*D[6] + v1.w*D[7];
    g_as1[i] = as;
    g_ad1[i] = ad;
    g_m1[i]  = lrelu(as + ad);      // self-loop edge initializes the max
}

__global__ void k_max1(int e) {
    int i = blockIdx.x * blockDim.x + threadIdx.x;
    if (i >= e * HEADS) return;
    int h = i & 7, ed = i >> 3;
    int s = g_src[ed], d = g_dst[ed];
    atomicMaxF(&g_m1[d * 8 + h], lrelu(g_as1[s * 8 + h] + g_ad1[d * 8 + h]));
}

__global__ void k_sinit1(int n) {
    int i = blockIdx.x * blockDim.x + threadIdx.x;
    if (i >= n * HEADS) return;
    g_s1[i] = expf(lrelu(g_as1[i] + g_ad1[i]) - g_m1[i]);   // self-loop term
}

__global__ void k_sum1(int e) {
    int i = blockIdx.x * blockDim.x + threadIdx.x;
    if (i >= e * HEADS) return;
    int h = i & 7, ed = i >> 3;
    int s = g_src[ed], d = g_dst[ed];
    float v = lrelu(g_as1[s * 8 + h] + g_ad1[d * 8 + h]);
    atomicAdd(&g_s1[d * 8 + h], expf(v - g_m1[d * 8 + h]));
}

// init out1 with the self-loop message: h1[n]*alpha_loop
__global__ void k_agginit1(int n) {
    int i = blockIdx.x * blockDim.x + threadIdx.x;
    if (i >= n * F1) return;
    int j = i >> 3;   // (node, head) index
    float w = expf(lrelu(g_as1[j] + g_ad1[j]) - g_m1[j]) / (g_s1[j] + 1e-16f);
    g_out1[i] = g_h1[i] * w;
}

__global__ void k_agg1(int e) {
    int i = blockIdx.x * blockDim.x + threadIdx.x;
    if (i >= e * HEADS) return;
    int h = i & 7, ed = i >> 3;
    int s = g_src[ed], d = g_dst[ed];
    int dj = d * 8 + h;
    float w = expf(lrelu(g_as1[s * 8 + h] + g_ad1[dj]) - g_m1[dj]) / (g_s1[dj] + 1e-16f);
    const float4 a = *(const float4*)(g_h1 + s * F1 + h * 8);
    const float4 b = *(const float4*)(g_h1 + s * F1 + h * 8 + 4);
    redAdd4(g_out1 + d * F1 + h * 8,     a.x * w, a.y * w, a.z * w, a.w * w);
    redAdd4(g_out1 + d * F1 + h * 8 + 4, b.x * w, b.y * w, b.z * w, b.w * w);
}

// h = elu(out1 + bias1), in place
__global__ void k_elu(const float* __restrict__ b1, int n) {
    int i = blockIdx.x * blockDim.x + threadIdx.x;
    if (i >= n * F1) return;
    float t = g_out1[i] + __ldg(&b1[i & 63]);
    g_out1[i] = t > 0.f ? t : expm1f(t);
}

// ------------------------- layer 2 ----------------------------------------
// h2 = h @ W2 ; attention logits (single head); self-loop max init
__global__ void k_gemm2(const float* __restrict__ W2,
                        const float* __restrict__ asrc, const float* __restrict__ adst, int n) {
    __shared__ float sW[F1 * DIM], sS[DIM], sD[DIM];
    for (int i = threadIdx.x; i < F1 * DIM; i += blockDim.x) sW[i] = W2[i];
    if (threadIdx.x < DIM) { sS[threadIdx.x] = asrc[threadIdx.x]; sD[threadIdx.x] = adst[threadIdx.x]; }
    __syncthreads();
    int nidx = blockIdx.x * blockDim.x + threadIdx.x;
    if (nidx >= n) return;
    float acc[DIM] = {0.f,0.f,0.f,0.f,0.f,0.f,0.f,0.f};
    const float* row = g_out1 + nidx * F1;
#pragma unroll
    for (int k = 0; k < F1; k += 4) {
        float4 t = *(const float4*)(row + k);
#pragma unroll
        for (int c = 0; c < DIM; c++)
            acc[c] += t.x * sW[k * 8 + c] + t.y * sW[(k + 1) * 8 + c]
                    + t.z * sW[(k + 2) * 8 + c] + t.w * sW[(k + 3) * 8 + c];
    }
    float as = 0.f, ad = 0.f;
#pragma unroll
    for (int c = 0; c < DIM; c++) {
        as += acc[c] * sS[c];
        ad += acc[c] * sD[c];
        g_h2[nidx * DIM + c] = acc[c];
    }
    g_as2[nidx] = as;
    g_ad2[nidx] = ad;
    g_m2[nidx]  = lrelu(as + ad);
}

__global__ void k_max2(int e) {
    int i = blockIdx.x * blockDim.x + threadIdx.x;
    if (i >= e) return;
    int s = g_src[i], d = g_dst[i];
    atomicMaxF(&g_m2[d], lrelu(g_as2[s] + g_ad2[d]));
}

__global__ void k_sinit2(int n) {
    int i = blockIdx.x * blockDim.x + threadIdx.x;
    if (i >= n) return;
    g_s2[i] = expf(lrelu(g_as2[i] + g_ad2[i]) - g_m2[i]);
}

__global__ void k_sum2(int e) {
    int i = blockIdx.x * blockDim.x + threadIdx.x;
    if (i >= e) return;
    int s = g_src[i], d = g_dst[i];
    atomicAdd(&g_s2[d], expf(lrelu(g_as2[s] + g_ad2[d]) - g_m2[d]));
}

// out = h2*alpha_loop + bias2
__global__ void k_outinit(const float* __restrict__ b2, int n, float* __restrict__ out) {
    int i = blockIdx.x * blockDim.x + threadIdx.x;
    if (i >= n * DIM) return;
    int nd = i >> 3, c = i & 7;
    float w = expf(lrelu(g_as2[nd] + g_ad2[nd]) - g_m2[nd]) / (g_s2[nd] + 1e-16f);
    out[i] = g_h2[i] * w + __ldg(&b2[c]);
}

__global__ void k_agg2(int e, float* __restrict__ out) {
    int i = blockIdx.x * blockDim.x + threadIdx.x;
    if (i >= e) return;
    int s = g_src[i], d = g_dst[i];
    float w = expf(lrelu(g_as2[s] + g_ad2[d]) - g_m2[d]) / (g_s2[d] + 1e-16f);
    const float4 a = *(const float4*)(g_h2 + s * DIM);
    const float4 b = *(const float4*)(g_h2 + s * DIM + 4);
    redAdd4(out + d * DIM,     a.x * w, a.y * w, a.z * w, a.w * w);
    redAdd4(out + d * DIM + 4, b.x * w, b.y * w, b.z * w, b.w * w);
}

// ------------------------- launch -----------------------------------------
extern "C" void kernel_launch(void* const* d_in, const int* in_sizes, int n_in,
                              void* d_out, int out_size) {
    const float* x   = (const float*)d_in[0];
    const void*  ei  = d_in[1];
    const float* W1  = (const float*)d_in[2];
    const float* as1 = (const float*)d_in[3];
    const float* ad1 = (const float*)d_in[4];
    const float* b1  = (const float*)d_in[5];
    const float* W2  = (const float*)d_in[6];
    const float* as2 = (const float*)d_in[7];
    const float* ad2 = (const float*)d_in[8];
    const float* b2  = (const float*)d_in[9];
    float* out = (float*)d_out;

    int n = in_sizes[0] / F_IN;
    int e = in_sizes[1] / 2;
    const int B = 256;
    auto g = [&](long long t) { return (unsigned)((t + B - 1) / B); };

    k_detect<<<1, 32>>>((const unsigned long long*)ei);
    k_convert<<<g(e), B>>>(ei, e);

    // layer 1
    k_gemm1   <<<g((long long)n * F1), B>>>(x, W1, n);
    k_alpha1  <<<g((long long)n * HEADS), B>>>(as1, ad1, n);
    k_max1    <<<g((long long)e * HEADS), B>>>(e);
    k_sinit1  <<<g((long long)n * HEADS), B>>>(n);
    k_sum1    <<<g((long long)e * HEADS), B>>>(e);
    k_agginit1<<<g((long long)n * F1), B>>>(n);
    k_agg1    <<<g((long long)e * HEADS), B>>>(e);
    k_elu     <<<g((long long)n * F1), B>>>(b1, n);

    // layer 2
    k_gemm2   <<<g(n), B>>>(W2, as2, ad2, n);
    k_max2    <<<g(e), B>>>(e);
    k_sinit2  <<<g(n), B>>>(n);
    k_sum2    <<<g(e), B>>>(e);
    k_outinit <<<g((long long)n * DIM), B>>>(b2, n, out);
    k_agg2    <<<g(e), B>>>(e, out);
}

// round 4
// speedup vs baseline: 1.5032x; 1.5032x over previous
#include <cuda_runtime.h>

#define F_IN  14
#define HEADS 8
#define DIM   8
#define F1    64          // HEADS*DIM
#define NEG   0.2f
#define MAXN  100000
#define MAXE  1600000

// ------------------------- scratch (device globals; no allocs) -------------
__device__ float g_h1  [MAXN * F1];     // layer1 linear output [N,64]
__device__ float g_out1[MAXN * F1];     // layer1 unnormalized acc, then ELU'd h
__device__ float g_as1 [MAXN * HEADS];
__device__ float g_ad1 [MAXN * HEADS];
__device__ float g_s1  [MAXN * HEADS];  // unnormalized weight sums
__device__ float g_h2  [MAXN * DIM];    // layer2 linear output [N,8]
__device__ float g_as2 [MAXN];
__device__ float g_ad2 [MAXN];
__device__ float g_s2  [MAXN];
__device__ int   g_src [MAXE];
__device__ int   g_dst [MAXE];
__device__ int   g_is64;

// ------------------------- helpers ----------------------------------------
__device__ __forceinline__ float lrelu(float x) { return x > 0.f ? x : NEG * x; }

// vectorized global reduction (sm_90+): 4 floats per RED op
__device__ __forceinline__ void redAdd4(float* a, float x, float y, float z, float w) {
    asm volatile("red.global.add.v4.f32 [%0], {%1,%2,%3,%4};"
                 :: "l"(a), "f"(x), "f"(y), "f"(z), "f"(w) : "memory");
}

// ------------------------- edge dtype detect + convert ---------------------
__global__ void k_detect(const unsigned long long* p) {
    if (threadIdx.x == 0) {
        int is64 = 1;
        for (int i = 0; i < 64; i++)
            if (p[i] >> 32) { is64 = 0; break; }
        g_is64 = is64;
    }
}

__global__ void k_convert(const void* ei, int e) {
    int i = blockIdx.x * blockDim.x + threadIdx.x;
    if (i >= e) return;
    if (g_is64) {
        const long long* p = (const long long*)ei;
        g_src[i] = (int)p[i];
        g_dst[i] = (int)p[e + i];
    } else {
        const int* p = (const int*)ei;
        g_src[i] = p[i];
        g_dst[i] = p[e + i];
    }
}

// ------------------------- layer 1 ----------------------------------------
// h1 = x @ W1   (thread per (node, outcol); x row broadcast-loaded via L1)
__global__ void k_gemm1(const float* __restrict__ x, const float* __restrict__ W1, int n) {
    __shared__ float sW[F_IN * F1];
    for (int i = threadIdx.x; i < F_IN * F1; i += blockDim.x) sW[i] = W1[i];
    __syncthreads();
    int i = blockIdx.x * blockDim.x + threadIdx.x;
    if (i >= n * F1) return;
    int node = i >> 6, c = i & 63;
    const float* xr = x + node * F_IN;
    float acc = 0.f;
#pragma unroll
    for (int k = 0; k < F_IN; k++) acc += xr[k] * sW[k * F1 + c];
    g_h1[i] = acc;
}

// per (node, head): logit halves + self-loop init of s and the accumulator
__global__ void k_prep1(const float* __restrict__ asrc, const float* __restrict__ adst, int n) {
    __shared__ float sS[64], sD[64];
    if (threadIdx.x < 64) { sS[threadIdx.x] = asrc[threadIdx.x]; sD[threadIdx.x] = adst[threadIdx.x]; }
    __syncthreads();
    int i = blockIdx.x * blockDim.x + threadIdx.x;
    if (i >= n * HEADS) return;
    int h = i & 7;
    float4 v0 = *(const float4*)(g_h1 + i * 8);
    float4 v1 = *(const float4*)(g_h1 + i * 8 + 4);
    const float* S = sS + h * 8;
    const float* D = sD + h * 8;
    float as = v0.x*S[0] + v0.y*S[1] + v0.z*S[2] + v0.w*S[3]
             + v1.x*S[4] + v1.y*S[5] + v1.z*S[6] + v1.w*S[7];
    float ad = v0.x*D[0] + v0.y*D[1] + v0.z*D[2] + v0.w*D[3]
             + v1.x*D[4] + v1.y*D[5] + v1.z*D[6] + v1.w*D[7];
    g_as1[i] = as;
    g_ad1[i] = ad;
    float wl = __expf(lrelu(as + ad));       // self-loop weight (unnormalized)
    g_s1[i] = wl;
    float4 o0 = make_float4(v0.x*wl, v0.y*wl, v0.z*wl, v0.w*wl);
    float4 o1 = make_float4(v1.x*wl, v1.y*wl, v1.z*wl, v1.w*wl);
    *(float4*)(g_out1 + i * 8)     = o0;
    *(float4*)(g_out1 + i * 8 + 4) = o1;
}

// single fused edge pass: unnormalized weighted scatter + weight-sum scatter
__global__ void k_edge1(int e) {
    int i = blockIdx.x * blockDim.x + threadIdx.x;
    if (i >= e * HEADS) return;
    int h = i & 7, ed = i >> 3;
    int s = g_src[ed], d = g_dst[ed];
    float w = __expf(lrelu(g_as1[s * 8 + h] + g_ad1[d * 8 + h]));
    const float4 a = *(const float4*)(g_h1 + s * F1 + h * 8);
    const float4 b = *(const float4*)(g_h1 + s * F1 + h * 8 + 4);
    redAdd4(g_out1 + d * F1 + h * 8,     a.x * w, a.y * w, a.z * w, a.w * w);
    redAdd4(g_out1 + d * F1 + h * 8 + 4, b.x * w, b.y * w, b.z * w, b.w * w);
    atomicAdd(&g_s1[d * 8 + h], w);
}

// normalize + bias + ELU, in place (g_out1 becomes layer-2 input h)
__global__ void k_fin1(const float* __restrict__ b1, int n) {
    int i = blockIdx.x * blockDim.x + threadIdx.x;
    if (i >= n * F1) return;
    float t = g_out1[i] / g_s1[i >> 3] + __ldg(&b1[i & 63]);
    g_out1[i] = t > 0.f ? t : expm1f(t);
}

// ------------------------- layer 2 ----------------------------------------
// h2 = h @ W2 ; logits (single head); self-loop init of s2 and out accumulator
__global__ void k_gemm2(const float* __restrict__ W2,
                        const float* __restrict__ asrc, const float* __restrict__ adst,
                        int n, float* __restrict__ out) {
    __shared__ float sW[F1 * DIM], sS[DIM], sD[DIM];
    for (int i = threadIdx.x; i < F1 * DIM; i += blockDim.x) sW[i] = W2[i];
    if (threadIdx.x < DIM) { sS[threadIdx.x] = asrc[threadIdx.x]; sD[threadIdx.x] = adst[threadIdx.x]; }
    __syncthreads();
    int nidx = blockIdx.x * blockDim.x + threadIdx.x;
    if (nidx >= n) return;
    float acc[DIM] = {0.f,0.f,0.f,0.f,0.f,0.f,0.f,0.f};
    const float* row = g_out1 + nidx * F1;
#pragma unroll
    for (int k = 0; k < F1; k += 4) {
        float4 t = *(const float4*)(row + k);
#pragma unroll
        for (int c = 0; c < DIM; c++)
            acc[c] += t.x * sW[k * 8 + c] + t.y * sW[(k + 1) * 8 + c]
                    + t.z * sW[(k + 2) * 8 + c] + t.w * sW[(k + 3) * 8 + c];
    }
    float as = 0.f, ad = 0.f;
#pragma unroll
    for (int c = 0; c < DIM; c++) {
        as += acc[c] * sS[c];
        ad += acc[c] * sD[c];
        g_h2[nidx * DIM + c] = acc[c];
    }
    g_as2[nidx] = as;
    g_ad2[nidx] = ad;
    float wl = __expf(lrelu(as + ad));
    g_s2[nidx] = wl;
#pragma unroll
    for (int c = 0; c < DIM; c++) out[nidx * DIM + c] = acc[c] * wl;
}

__global__ void k_edge2(int e, float* __restrict__ out) {
    int i = blockIdx.x * blockDim.x + threadIdx.x;
    if (i >= e) return;
    int s = g_src[i], d = g_dst[i];
    float w = __expf(lrelu(g_as2[s] + g_ad2[d]));
    const float4 a = *(const float4*)(g_h2 + s * DIM);
    const float4 b = *(const float4*)(g_h2 + s * DIM + 4);
    redAdd4(out + d * DIM,     a.x * w, a.y * w, a.z * w, a.w * w);
    redAdd4(out + d * DIM + 4, b.x * w, b.y * w, b.z * w, b.w * w);
    atomicAdd(&g_s2[d], w);
}

__global__ void k_fin2(const float* __restrict__ b2, int n, float* __restrict__ out) {
    int i = blockIdx.x * blockDim.x + threadIdx.x;
    if (i >= n * DIM) return;
    out[i] = out[i] / g_s2[i >> 3] + __ldg(&b2[i & 7]);
}

// ------------------------- launch -----------------------------------------
extern "C" void kernel_launch(void* const* d_in, const int* in_sizes, int n_in,
                              void* d_out, int out_size) {
    const float* x   = (const float*)d_in[0];
    const void*  ei  = d_in[1];
    const float* W1  = (const float*)d_in[2];
    const float* as1 = (const float*)d_in[3];
    const float* ad1 = (const float*)d_in[4];
    const float* b1  = (const float*)d_in[5];
    const float* W2  = (const float*)d_in[6];
    const float* as2 = (const float*)d_in[7];
    const float* ad2 = (const float*)d_in[8];
    const float* b2  = (const float*)d_in[9];
    float* out = (float*)d_out;

    int n = in_sizes[0] / F_IN;
    int e = in_sizes[1] / 2;
    const int B = 256;
    auto g = [&](long long t) { return (unsigned)((t + B - 1) / B); };

    k_detect <<<1, 32>>>((const unsigned long long*)ei);
    k_convert<<<g(e), B>>>(ei, e);

    // layer 1: gemm -> prep(+self-loop init) -> ONE edge pass -> normalize+ELU
    k_gemm1 <<<g((long long)n * F1), B>>>(x, W1, n);
    k_prep1 <<<g((long long)n * HEADS), B>>>(as1, ad1, n);
    k_edge1 <<<g((long long)e * HEADS), B>>>(e);
    k_fin1  <<<g((long long)n * F1), B>>>(b1, n);

    // layer 2: gemm(+logits+init) -> ONE edge pass -> normalize+bias
    k_gemm2 <<<g(n), B>>>(W2, as2, ad2, n, out);
    k_edge2 <<<g(e), B>>>(e, out);
    k_fin2  <<<g((long long)n * DIM), B>>>(b2, n, out);
}

// round 5
// speedup vs baseline: 1.5860x; 1.0550x over previous
#include <cuda_runtime.h>

#define F_IN  14
#define HEADS 8
#define DIM   8
#define F1    64          // HEADS*DIM
#define NEG   0.2f
#define MAXN  100000
#define MAXE  1600000

// ------------------------- scratch (device globals; no allocs) -------------
__device__ float g_h1  [MAXN * F1];     // layer1 linear output [N,64]
__device__ float g_out1[MAXN * F1];     // layer1 unnormalized accumulator
__device__ float g_as1 [MAXN * HEADS];
__device__ float g_ad1 [MAXN * HEADS];
__device__ float g_s1  [MAXN * HEADS];  // unnormalized weight sums
__device__ float g_h2  [MAXN * DIM];    // layer2 linear output [N,8]
__device__ float g_as2 [MAXN];
__device__ float g_ad2 [MAXN];
__device__ float g_s2  [MAXN];
__device__ int   g_src [MAXE];
__device__ int   g_dst [MAXE];
__device__ int   g_is64;

// ------------------------- helpers ----------------------------------------
__device__ __forceinline__ float lrelu(float x) { return x > 0.f ? x : NEG * x; }

__device__ __forceinline__ void redAdd4(float* a, float x, float y, float z, float w) {
    asm volatile("red.global.add.v4.f32 [%0], {%1,%2,%3,%4};"
                 :: "l"(a), "f"(x), "f"(y), "f"(z), "f"(w) : "memory");
}

// ------------------------- edge dtype detect + convert ---------------------
__global__ void k_detect(const unsigned long long* p) {
    if (threadIdx.x == 0) {
        int is64 = 1;
        for (int i = 0; i < 64; i++)
            if (p[i] >> 32) { is64 = 0; break; }
        g_is64 = is64;
    }
}

__global__ void k_convert(const void* ei, int e) {
    int i = blockIdx.x * blockDim.x + threadIdx.x;
    if (i >= e) return;
    if (g_is64) {
        const long long* p = (const long long*)ei;
        g_src[i] = (int)p[i];
        g_dst[i] = (int)p[e + i];
    } else {
        const int* p = (const int*)ei;
        g_src[i] = p[i];
        g_dst[i] = p[e + i];
    }
}

// ------------------------- layer 1: fused gemm + logits + self-loop init ---
// 64 threads per node (block = 4 nodes). Each thread owns one output column.
// 8-lane butterfly reduces per-head attention logits in-register.
__global__ void __launch_bounds__(256) k_l1(const float* __restrict__ x,
                                            const float* __restrict__ W1,
                                            const float* __restrict__ asrc,
                                            const float* __restrict__ adst, int n) {
    __shared__ float sW[F_IN * F1];
    __shared__ float sS[F1], sD[F1];
    int tid = threadIdx.x;
    for (int i = tid; i < F_IN * F1; i += 256) sW[i] = W1[i];
    if (tid < F1) { sS[tid] = asrc[tid]; sD[tid] = adst[tid]; }
    __syncthreads();

    int node = blockIdx.x * 4 + (tid >> 6);
    int c = tid & 63;
    if (node >= n) return;          // warp-uniform (64 threads per node)

    const float* xr = x + node * F_IN;
    float acc = 0.f;
#pragma unroll
    for (int k = 0; k < F_IN; k++) acc += xr[k] * sW[k * F1 + c];
    g_h1[node * F1 + c] = acc;

    // per-head logit reduction over the 8 lanes of this head
    float as = acc * sS[c], ad = acc * sD[c];
#pragma unroll
    for (int m = 1; m < 8; m <<= 1) {
        as += __shfl_xor_sync(0xffffffffu, as, m, 8);
        ad += __shfl_xor_sync(0xffffffffu, ad, m, 8);
    }
    float wl = __expf(lrelu(as + ad));      // self-loop weight
    if ((c & 7) == 0) {
        int j = node * HEADS + (c >> 3);
        g_as1[j] = as;
        g_ad1[j] = ad;
        g_s1[j]  = wl;
    }
    g_out1[node * F1 + c] = acc * wl;       // self-loop message init
}

// ------------------------- layer 1: single fused edge pass -----------------
// 8 threads per edge (one per head). Weighted scatter via v4 REDs; the 8
// per-head weights (contiguous in g_s1) are combined via shfl into 2 v4 REDs.
__global__ void __launch_bounds__(256) k_edge1(int e) {
    int i = blockIdx.x * blockDim.x + threadIdx.x;
    bool valid = i < e * HEADS;
    int h = i & 7, ed = valid ? (i >> 3) : 0;
    int s = g_src[ed], d = g_dst[ed];
    float w = 0.f;
    if (valid) {
        w = __expf(lrelu(g_as1[s * 8 + h] + g_ad1[d * 8 + h]));
        const float4 a = *(const float4*)(g_h1 + s * F1 + h * 8);
        const float4 b = *(const float4*)(g_h1 + s * F1 + h * 8 + 4);
        redAdd4(g_out1 + d * F1 + h * 8,     a.x * w, a.y * w, a.z * w, a.w * w);
        redAdd4(g_out1 + d * F1 + h * 8 + 4, b.x * w, b.y * w, b.z * w, b.w * w);
    }
    // combine 4 neighboring weights -> one v4 RED (lanes h%4==0 issue)
    float w1 = __shfl_xor_sync(0xffffffffu, w,  1);
    float w2 = __shfl_xor_sync(0xffffffffu, w,  2);
    float w3 = __shfl_xor_sync(0xffffffffu, w1, 2);
    if (valid && (h & 3) == 0)
        redAdd4(&g_s1[d * 8 + h], w, w1, w2, w3);
}

// ------------------------- layer 2: fused normalize+ELU+gemm+logits+init ---
__global__ void __launch_bounds__(256) k_l2(const float* __restrict__ W2,
                                            const float* __restrict__ b1,
                                            const float* __restrict__ asrc,
                                            const float* __restrict__ adst,
                                            int n, float* __restrict__ out) {
    __shared__ float sW[F1 * DIM], sB[F1], sS[DIM], sD[DIM];
    int tid = threadIdx.x;
    for (int i = tid; i < F1 * DIM; i += 256) sW[i] = W2[i];
    if (tid < F1) sB[tid] = b1[tid];
    if (tid < DIM) { sS[tid] = asrc[tid]; sD[tid] = adst[tid]; }
    __syncthreads();

    int nidx = blockIdx.x * blockDim.x + tid;
    if (nidx >= n) return;

    // per-head normalizers
    float rs[HEADS];
    {
        float4 s0 = *(const float4*)(g_s1 + nidx * 8);
        float4 s1 = *(const float4*)(g_s1 + nidx * 8 + 4);
        rs[0] = __fdividef(1.f, s0.x); rs[1] = __fdividef(1.f, s0.y);
        rs[2] = __fdividef(1.f, s0.z); rs[3] = __fdividef(1.f, s0.w);
        rs[4] = __fdividef(1.f, s1.x); rs[5] = __fdividef(1.f, s1.y);
        rs[6] = __fdividef(1.f, s1.z); rs[7] = __fdividef(1.f, s1.w);
    }

    float acc[DIM] = {0.f,0.f,0.f,0.f,0.f,0.f,0.f,0.f};
    const float* row = g_out1 + nidx * F1;
#pragma unroll
    for (int k = 0; k < F1; k += 4) {
        float4 t = *(const float4*)(row + k);
        float r = rs[k >> 3];                       // float4 never crosses a head
        t.x = t.x * r + sB[k];     t.x = t.x > 0.f ? t.x : expm1f(t.x);
        t.y = t.y * r + sB[k + 1]; t.y = t.y > 0.f ? t.y : expm1f(t.y);
        t.z = t.z * r + sB[k + 2]; t.z = t.z > 0.f ? t.z : expm1f(t.z);
        t.w = t.w * r + sB[k + 3]; t.w = t.w > 0.f ? t.w : expm1f(t.w);
#pragma unroll
        for (int c = 0; c < DIM; c++)
            acc[c] += t.x * sW[k * 8 + c] + t.y * sW[(k + 1) * 8 + c]
                    + t.z * sW[(k + 2) * 8 + c] + t.w * sW[(k + 3) * 8 + c];
    }

    float as = 0.f, ad = 0.f;
#pragma unroll
    for (int c = 0; c < DIM; c++) {
        as += acc[c] * sS[c];
        ad += acc[c] * sD[c];
        g_h2[nidx * DIM + c] = acc[c];
    }
    g_as2[nidx] = as;
    g_ad2[nidx] = ad;
    float wl = __expf(lrelu(as + ad));
    g_s2[nidx] = wl;
#pragma unroll
    for (int c = 0; c < DIM; c++) out[nidx * DIM + c] = acc[c] * wl;
}

// ------------------------- layer 2: single fused edge pass -----------------
__global__ void __launch_bounds__(256) k_edge2(int e, float* __restrict__ out) {
    int i = blockIdx.x * blockDim.x + threadIdx.x;
    if (i >= e) return;
    int s = g_src[i], d = g_dst[i];
    float w = __expf(lrelu(g_as2[s] + g_ad2[d]));
    const float4 a = *(const float4*)(g_h2 + s * DIM);
    const float4 b = *(const float4*)(g_h2 + s * DIM + 4);
    redAdd4(out + d * DIM,     a.x * w, a.y * w, a.z * w, a.w * w);
    redAdd4(out + d * DIM + 4, b.x * w, b.y * w, b.z * w, b.w * w);
    atomicAdd(&g_s2[d], w);
}

__global__ void k_fin2(const float* __restrict__ b2, int n, float* __restrict__ out) {
    int i = blockIdx.x * blockDim.x + threadIdx.x;
    if (i >= n * DIM) return;
    out[i] = out[i] / g_s2[i >> 3] + __ldg(&b2[i & 7]);
}

// ------------------------- launch -----------------------------------------
extern "C" void kernel_launch(void* const* d_in, const int* in_sizes, int n_in,
                              void* d_out, int out_size) {
    const float* x   = (const float*)d_in[0];
    const void*  ei  = d_in[1];
    const float* W1  = (const float*)d_in[2];
    const float* as1 = (const float*)d_in[3];
    const float* ad1 = (const float*)d_in[4];
    const float* b1  = (const float*)d_in[5];
    const float* W2  = (const float*)d_in[6];
    const float* as2 = (const float*)d_in[7];
    const float* ad2 = (const float*)d_in[8];
    const float* b2  = (const float*)d_in[9];
    float* out = (float*)d_out;

    int n = in_sizes[0] / F_IN;
    int e = in_sizes[1] / 2;
    const int B = 256;
    auto g = [&](long long t) { return (unsigned)((t + B - 1) / B); };

    k_detect <<<1, 32>>>((const unsigned long long*)ei);
    k_convert<<<g(e), B>>>(ei, e);

    // layer 1
    k_l1    <<<(n + 3) / 4, B>>>(x, W1, as1, ad1, n);
    k_edge1 <<<g((long long)e * HEADS), B>>>(e);

    // layer 2 (fin1 folded into k_l2)
    k_l2    <<<g(n), B>>>(W2, b1, as2, ad2, n, out);
    k_edge2 <<<g(e), B>>>(e, out);
    k_fin2  <<<g((long long)n * DIM), B>>>(b2, n, out);
}